// round 1
// baseline (speedup 1.0000x reference)
#include <cuda_runtime.h>
#include <math.h>

#define ROWS 8192
#define COLS 256
#define BM 128
#define BN 128
#define BK 16
#define TM 8
#define TN 8
#define TILES (ROWS / BM)        /* 64 */
#define NPART (TILES * TILES)    /* 4096 */
#define GAMMA 1.0f

// scratch (no allocations allowed in kernel_launch)
__device__ float g_x2N[ROWS];
__device__ float g_x2R[ROWS];
__device__ float g_part[3 * NPART];

// ---------------------------------------------------------------------------
// Row squared-norms: one warp per row, shuffle reduce.
// ---------------------------------------------------------------------------
__global__ void rownorm_kernel(const float* __restrict__ A, float* __restrict__ out) {
    int warps_per_block = blockDim.x >> 5;
    int row = blockIdx.x * warps_per_block + (threadIdx.x >> 5);
    int lane = threadIdx.x & 31;
    if (row >= ROWS) return;
    const float* p = A + (size_t)row * COLS;
    float s = 0.f;
#pragma unroll
    for (int k = lane; k < COLS; k += 32) {
        float v = p[k];
        s = fmaf(v, v, s);
    }
#pragma unroll
    for (int o = 16; o > 0; o >>= 1)
        s += __shfl_xor_sync(0xffffffffu, s, o);
    if (lane == 0) out[row] = s;
}

// ---------------------------------------------------------------------------
// Fused tile GEMM + exp-sum.
// blockIdx.x = tile_j, blockIdx.y = tile_i, blockIdx.z = pass (0=NN,1=RR,2=NR)
// Symmetric passes compute only tj >= ti; strictly-upper tiles weighted 2x.
// ---------------------------------------------------------------------------
__global__ __launch_bounds__(256, 2)
void mmd_tile_kernel(const float* __restrict__ Nmat, const float* __restrict__ Rmat) {
    const int pass = blockIdx.z;
    const float *A, *B, *x2a, *x2b;
    bool sym;
    if (pass == 0)      { A = Nmat; B = Nmat; x2a = g_x2N; x2b = g_x2N; sym = true;  }
    else if (pass == 1) { A = Rmat; B = Rmat; x2a = g_x2R; x2b = g_x2R; sym = true;  }
    else                { A = Nmat; B = Rmat; x2a = g_x2N; x2b = g_x2R; sym = false; }

    const int ti = blockIdx.y, tj = blockIdx.x;
    const int slot = pass * NPART + ti * TILES + tj;
    if (sym && tj < ti) {
        if (threadIdx.x == 0) g_part[slot] = 0.f;
        return;
    }

    __shared__ float As[BK][BM];
    __shared__ float Bs[BK][BN];

    const int tid = threadIdx.x;
    const int tx = tid & 15;   // -> n
    const int ty = tid >> 4;   // -> m

    // gmem loader mapping: 4 threads cover one row's 16 k-columns as float4s
    const int lrow  = tid >> 2;          // 0..63 (and +64)
    const int lcol4 = (tid & 3) * 4;     // 0,4,8,12
    const float* Aptr = A + (size_t)(ti * BM + lrow) * COLS + lcol4;
    const float* Bptr = B + (size_t)(tj * BN + lrow) * COLS + lcol4;

    float acc[TM][TN];
#pragma unroll
    for (int i = 0; i < TM; i++)
#pragma unroll
        for (int j = 0; j < TN; j++) acc[i][j] = 0.f;

    for (int kb = 0; kb < COLS; kb += BK) {
        float4 a0 = *(const float4*)(Aptr + kb);
        float4 a1 = *(const float4*)(Aptr + kb + (size_t)64 * COLS);
        float4 b0 = *(const float4*)(Bptr + kb);
        float4 b1 = *(const float4*)(Bptr + kb + (size_t)64 * COLS);

        __syncthreads();
        As[lcol4 + 0][lrow] = a0.x; As[lcol4 + 1][lrow] = a0.y;
        As[lcol4 + 2][lrow] = a0.z; As[lcol4 + 3][lrow] = a0.w;
        As[lcol4 + 0][lrow + 64] = a1.x; As[lcol4 + 1][lrow + 64] = a1.y;
        As[lcol4 + 2][lrow + 64] = a1.z; As[lcol4 + 3][lrow + 64] = a1.w;
        Bs[lcol4 + 0][lrow] = b0.x; Bs[lcol4 + 1][lrow] = b0.y;
        Bs[lcol4 + 2][lrow] = b0.z; Bs[lcol4 + 3][lrow] = b0.w;
        Bs[lcol4 + 0][lrow + 64] = b1.x; Bs[lcol4 + 1][lrow + 64] = b1.y;
        Bs[lcol4 + 2][lrow + 64] = b1.z; Bs[lcol4 + 3][lrow + 64] = b1.w;
        __syncthreads();

#pragma unroll
        for (int k = 0; k < BK; k++) {
            // split 4+4 fragments -> conflict-free LDS.128
            float4 af0 = *(const float4*)&As[k][ty * 4];
            float4 af1 = *(const float4*)&As[k][ty * 4 + 64];
            float4 bf0 = *(const float4*)&Bs[k][tx * 4];
            float4 bf1 = *(const float4*)&Bs[k][tx * 4 + 64];
            float a[TM] = {af0.x, af0.y, af0.z, af0.w, af1.x, af1.y, af1.z, af1.w};
            float b[TN] = {bf0.x, bf0.y, bf0.z, bf0.w, bf1.x, bf1.y, bf1.z, bf1.w};
#pragma unroll
            for (int i = 0; i < TM; i++)
#pragma unroll
                for (int j = 0; j < TN; j++)
                    acc[i][j] = fmaf(a[i], b[j], acc[i][j]);
        }
    }

    // epilogue: d2 = x2_i + y2_j - 2*dot ; contribute exp(-gamma*max(d2,0)) when not underflowed
    float x2r[TM], y2c[TN];
#pragma unroll
    for (int i = 0; i < TM; i++) {
        int r = ti * BM + ty * 4 + (i & 3) + ((i >> 2) * 64);
        x2r[i] = x2a[r];
    }
#pragma unroll
    for (int j = 0; j < TN; j++) {
        int c = tj * BN + tx * 4 + (j & 3) + ((j >> 2) * 64);
        y2c[j] = x2b[c];
    }

    float s = 0.f;
#pragma unroll
    for (int i = 0; i < TM; i++) {
#pragma unroll
        for (int j = 0; j < TN; j++) {
            float d2 = fmaf(-2.f, acc[i][j], x2r[i] + y2c[j]);
            if (d2 < 90.f) {            // exp underflows to 0 beyond this anyway
                d2 = fmaxf(d2, 0.f);
                s += __expf(-GAMMA * d2);
            }
        }
    }

    // deterministic block reduction (fixed shuffle tree + fixed-order warp sums)
#pragma unroll
    for (int o = 16; o > 0; o >>= 1)
        s += __shfl_xor_sync(0xffffffffu, s, o);

    __shared__ float wsum[8];
    if ((tid & 31) == 0) wsum[tid >> 5] = s;
    __syncthreads();
    if (tid == 0) {
        float t = 0.f;
#pragma unroll
        for (int w = 0; w < 8; w++) t += wsum[w];
        float weight = (sym && tj > ti) ? 2.f : 1.f;
        g_part[slot] = weight * t;
    }
}

// ---------------------------------------------------------------------------
// Final deterministic reduction + sqrt
// ---------------------------------------------------------------------------
__global__ void finalize_kernel(float* __restrict__ out) {
    __shared__ float sh[256];
    const int tid = threadIdx.x;
    float sums[3];
#pragma unroll
    for (int p = 0; p < 3; p++) {
        float s = 0.f;
        for (int idx = tid; idx < NPART; idx += 256)
            s += g_part[p * NPART + idx];
        sh[tid] = s;
        __syncthreads();
        for (int o = 128; o > 0; o >>= 1) {
            if (tid < o) sh[tid] += sh[tid + o];
            __syncthreads();
        }
        sums[p] = sh[0];
        __syncthreads();
    }
    if (tid == 0) {
        double inv = 1.0 / ((double)ROWS * (double)ROWS);
        double mmd = ((double)sums[0] + (double)sums[1] - 2.0 * (double)sums[2]) * inv;
        if (mmd < 0.0) mmd = 0.0;
        out[0] = (float)sqrt(mmd);
    }
}

// ---------------------------------------------------------------------------
extern "C" void kernel_launch(void* const* d_in, const int* in_sizes, int n_in,
                              void* d_out, int out_size) {
    const float* Nmat = (const float*)d_in[0];
    const float* Rmat = (const float*)d_in[1];
    float* out = (float*)d_out;
    (void)in_sizes; (void)n_in; (void)out_size;

    float* x2N; cudaGetSymbolAddress((void**)&x2N, g_x2N);
    float* x2R; cudaGetSymbolAddress((void**)&x2R, g_x2R);

    // row norms: 8 warps/block -> 32 rows/block? (256 thr = 8 warps -> 8 rows/block)
    {
        int warps_per_block = 8;
        int blocks = ROWS / warps_per_block;
        rownorm_kernel<<<blocks, warps_per_block * 32>>>(Nmat, x2N);
        rownorm_kernel<<<blocks, warps_per_block * 32>>>(Rmat, x2R);
    }

    dim3 grid(TILES, TILES, 3);
    mmd_tile_kernel<<<grid, 256>>>(Nmat, Rmat);

    finalize_kernel<<<1, 256>>>(out);
}

// round 3
// speedup vs baseline: 4.6641x; 4.6641x over previous
#include <cuda_runtime.h>
#include <cuda_bf16.h>
#include <cstdint>
#include <math.h>

#define ROWS 8192
#define COLS 256
#define BM 128
#define BN 128
#define BK 32
#define TILES 64                 /* 8192/128 */
#define NPART (TILES * TILES)    /* 4096 */
#define RARE_THRESH 32.0f

// ---------------------------------------------------------------------------
// device scratch
// ---------------------------------------------------------------------------
__device__ __align__(16) __nv_bfloat16 g_Nbf[ROWS * COLS];
__device__ __align__(16) __nv_bfloat16 g_Rbf[ROWS * COLS];
__device__ float g_x2N[ROWS];
__device__ float g_x2R[ROWS];
__device__ float g_part[3 * NPART];

// ---------------------------------------------------------------------------
// PTX helpers (base-arch only: cp.async, ldmatrix, mma.sync — no tcgen05)
// ---------------------------------------------------------------------------
__device__ __forceinline__ uint32_t smem_u32(const void* p) {
    uint32_t a;
    asm("{ .reg .u64 t; cvta.to.shared.u64 t, %1; cvt.u32.u64 %0, t; }" : "=r"(a) : "l"(p));
    return a;
}
#define CP16(dst, src) \
    asm volatile("cp.async.cg.shared.global [%0], [%1], 16;" :: "r"(dst), "l"(src) : "memory")
#define CP_COMMIT() asm volatile("cp.async.commit_group;" ::: "memory")
#define LDSM4(r, addr) \
    asm volatile("ldmatrix.sync.aligned.m8n8.x4.shared.b16 {%0,%1,%2,%3}, [%4];" \
        : "=r"((r)[0]), "=r"((r)[1]), "=r"((r)[2]), "=r"((r)[3]) : "r"(addr))
#define LDSM2(r, addr) \
    asm volatile("ldmatrix.sync.aligned.m8n8.x2.shared.b16 {%0,%1}, [%2];" \
        : "=r"((r)[0]), "=r"((r)[1]) : "r"(addr))
#define MMA16816(d, a, b) \
    asm volatile("mma.sync.aligned.m16n8k16.row.col.f32.bf16.bf16.f32 " \
        "{%0,%1,%2,%3}, {%4,%5,%6,%7}, {%8,%9}, {%0,%1,%2,%3};" \
        : "+f"((d)[0]), "+f"((d)[1]), "+f"((d)[2]), "+f"((d)[3]) \
        : "r"((a)[0]), "r"((a)[1]), "r"((a)[2]), "r"((a)[3]), "r"((b)[0]), "r"((b)[1]))

// ---------------------------------------------------------------------------
// Prep: fp32 -> bf16 row-major + exact fp32 row squared-norms.
// One warp per row. blockIdx.y: 0 = N, 1 = R.
// ---------------------------------------------------------------------------
__global__ void prep_kernel(const float* __restrict__ Nf, const float* __restrict__ Rf) {
    const float* src = blockIdx.y ? Rf : Nf;
    __nv_bfloat16* dst = blockIdx.y ? g_Rbf : g_Nbf;
    float* x2 = blockIdx.y ? g_x2R : g_x2N;

    int row = blockIdx.x * 8 + (threadIdx.x >> 5);
    int lane = threadIdx.x & 31;
    const float* p = src + (size_t)row * COLS + lane * 8;
    float4 v0 = *(const float4*)p;
    float4 v1 = *(const float4*)(p + 4);
    float s = 0.f;
    s = fmaf(v0.x, v0.x, s); s = fmaf(v0.y, v0.y, s);
    s = fmaf(v0.z, v0.z, s); s = fmaf(v0.w, v0.w, s);
    s = fmaf(v1.x, v1.x, s); s = fmaf(v1.y, v1.y, s);
    s = fmaf(v1.z, v1.z, s); s = fmaf(v1.w, v1.w, s);

    __align__(16) __nv_bfloat16 b[8];
    b[0] = __float2bfloat16(v0.x); b[1] = __float2bfloat16(v0.y);
    b[2] = __float2bfloat16(v0.z); b[3] = __float2bfloat16(v0.w);
    b[4] = __float2bfloat16(v1.x); b[5] = __float2bfloat16(v1.y);
    b[6] = __float2bfloat16(v1.z); b[7] = __float2bfloat16(v1.w);
    *(uint4*)(dst + (size_t)row * COLS + lane * 8) = *(const uint4*)b;

#pragma unroll
    for (int o = 16; o > 0; o >>= 1) s += __shfl_xor_sync(0xffffffffu, s, o);
    if (lane == 0) x2[row] = s;
}

// ---------------------------------------------------------------------------
// Fused bf16 HMMA Gram + screen + rare-path exact epilogue.
// grid (64, 64, 3); 256 threads; warp layout 2 (m) x 4 (n), warp tile 64x32.
// ---------------------------------------------------------------------------
__global__ __launch_bounds__(256)
void mmd_mma_kernel(const float* __restrict__ Nf, const float* __restrict__ Rf) {
    const int pass = blockIdx.z, ti = blockIdx.y, tj = blockIdx.x;
    const int slot = pass * NPART + ti * TILES + tj;
    const bool sym = (pass < 2);
    if (sym && tj < ti) {
        if (threadIdx.x == 0) g_part[slot] = 0.f;
        return;
    }

    const __nv_bfloat16 *Abf, *Bbf;
    const float *x2a, *x2b, *Af, *Bf;
    if (pass == 0)      { Abf = g_Nbf; Bbf = g_Nbf; x2a = g_x2N; x2b = g_x2N; Af = Nf; Bf = Nf; }
    else if (pass == 1) { Abf = g_Rbf; Bbf = g_Rbf; x2a = g_x2R; x2b = g_x2R; Af = Rf; Bf = Rf; }
    else                { Abf = g_Nbf; Bbf = g_Rbf; x2a = g_x2N; x2b = g_x2R; Af = Nf; Bf = Rf; }

    __shared__ __nv_bfloat16 As[2][BM * BK];
    __shared__ __nv_bfloat16 Bs[2][BN * BK];
    __shared__ float wsum[8];

    const int tid = threadIdx.x, wid = tid >> 5, lane = tid & 31;
    const uint32_t aS = smem_u32(As), bS = smem_u32(Bs);

    // gmem loader: thread covers (rows tid/4, tid/4+64) x chunk tid%4 (16B)
    const int lrow = tid >> 2;      // 0..63
    const int lchunk = tid & 3;
    const __nv_bfloat16* Ag = Abf + (size_t)(ti * BM) * COLS + lchunk * 8;
    const __nv_bfloat16* Bg = Bbf + (size_t)(tj * BN) * COLS + lchunk * 8;

    // swizzled 16B-chunk offset within a buffer: row*64B, chunk ^ ((row>>1)&3)
#define SWOFF(buf, row, chunk) \
    ((uint32_t)((((buf) * 128 + (row)) * 4 + ((chunk) ^ (((row) >> 1) & 3))) * 16))

    float acc[4][4][4];
#pragma unroll
    for (int mi = 0; mi < 4; mi++)
#pragma unroll
        for (int ni = 0; ni < 4; ni++)
#pragma unroll
            for (int r = 0; r < 4; r++) acc[mi][ni][r] = 0.f;

    const int wm = (wid & 1) * 64;
    const int wn = (wid >> 1) * 32;

    // ldmatrix per-thread source coords
    const int a_r = lane & 15, a_c = lane >> 4;          // A: row in 16-tile, chunk add
    const int b_r = lane & 7,  b_c = (lane >> 3) & 1;    // B: row in 8-tile, chunk add

    // prologue: stage 0
    {
        int r0 = lrow, r1 = lrow + 64;
        CP16(aS + SWOFF(0, r0, lchunk), Ag + (size_t)r0 * COLS);
        CP16(aS + SWOFF(0, r1, lchunk), Ag + (size_t)r1 * COLS);
        CP16(bS + SWOFF(0, r0, lchunk), Bg + (size_t)r0 * COLS);
        CP16(bS + SWOFF(0, r1, lchunk), Bg + (size_t)r1 * COLS);
        CP_COMMIT();
    }

#pragma unroll 1
    for (int it = 0; it < COLS / BK; it++) {
        if (it + 1 < COLS / BK) {
            int buf = (it + 1) & 1, kb = (it + 1) * BK;
            int r0 = lrow, r1 = lrow + 64;
            CP16(aS + SWOFF(buf, r0, lchunk), Ag + (size_t)r0 * COLS + kb);
            CP16(aS + SWOFF(buf, r1, lchunk), Ag + (size_t)r1 * COLS + kb);
            CP16(bS + SWOFF(buf, r0, lchunk), Bg + (size_t)r0 * COLS + kb);
            CP16(bS + SWOFF(buf, r1, lchunk), Bg + (size_t)r1 * COLS + kb);
            CP_COMMIT();
            asm volatile("cp.async.wait_group 1;" ::: "memory");
        } else {
            asm volatile("cp.async.wait_group 0;" ::: "memory");
        }
        __syncthreads();

        const int buf = it & 1;
#pragma unroll
        for (int s = 0; s < 2; s++) {
            uint32_t a_frag[4][4], b_frag[4][2];
#pragma unroll
            for (int mi = 0; mi < 4; mi++) {
                int r = wm + mi * 16 + a_r;
                LDSM4(a_frag[mi], aS + SWOFF(buf, r, 2 * s + a_c));
            }
#pragma unroll
            for (int ni = 0; ni < 4; ni++) {
                int r = wn + ni * 8 + b_r;
                LDSM2(b_frag[ni], bS + SWOFF(buf, r, 2 * s + b_c));
            }
#pragma unroll
            for (int mi = 0; mi < 4; mi++)
#pragma unroll
                for (int ni = 0; ni < 4; ni++)
                    MMA16816(acc[mi][ni], a_frag[mi], b_frag[ni]);
        }
        __syncthreads();
    }

    // ---- epilogue: screen d2, exact recompute of rare elements ----
    const int qr = lane >> 2, qc = (lane & 3) * 2;
    float x2i[8], x2j[8];
#pragma unroll
    for (int mi = 0; mi < 4; mi++) {
        x2i[mi * 2 + 0] = x2a[ti * BM + wm + mi * 16 + qr];
        x2i[mi * 2 + 1] = x2a[ti * BM + wm + mi * 16 + qr + 8];
    }
#pragma unroll
    for (int ni = 0; ni < 4; ni++) {
        x2j[ni * 2 + 0] = x2b[tj * BN + wn + ni * 8 + qc];
        x2j[ni * 2 + 1] = x2b[tj * BN + wn + ni * 8 + qc + 1];
    }

    const bool diag = sym && (ti == tj);
    const float base_w = sym ? 2.f : 1.f;
    float ssum = 0.f;
#pragma unroll
    for (int mi = 0; mi < 4; mi++) {
#pragma unroll
        for (int ni = 0; ni < 4; ni++) {
#pragma unroll
            for (int r = 0; r < 4; r++) {
                float x2s = x2i[mi * 2 + (r >> 1)] + x2j[ni * 2 + (r & 1)];
                float d2 = fmaf(-2.f, acc[mi][ni][r], x2s);
                if (d2 < RARE_THRESH) {
                    int i = ti * BM + wm + mi * 16 + qr + (r >> 1) * 8;
                    int j = tj * BN + wn + ni * 8 + qc + (r & 1);
                    const float* ar = Af + (size_t)i * COLS;
                    const float* br = Bf + (size_t)j * COLS;
                    float pd = 0.f;
                    for (int k = 0; k < COLS; k += 4) {
                        float4 av = *(const float4*)(ar + k);
                        float4 bv = *(const float4*)(br + k);
                        pd = fmaf(av.x, bv.x, pd); pd = fmaf(av.y, bv.y, pd);
                        pd = fmaf(av.z, bv.z, pd); pd = fmaf(av.w, bv.w, pd);
                    }
                    float d2p = fmaxf(fmaf(-2.f, pd, x2s), 0.f);
                    float w = base_w;
                    if (diag) w = (j > i) ? 2.f : ((j == i) ? 1.f : 0.f);
                    ssum += w * __expf(-d2p);
                }
            }
        }
    }

    // deterministic block reduction
#pragma unroll
    for (int o = 16; o > 0; o >>= 1) ssum += __shfl_xor_sync(0xffffffffu, ssum, o);
    if (lane == 0) wsum[wid] = ssum;
    __syncthreads();
    if (tid == 0) {
        float t = 0.f;
#pragma unroll
        for (int w = 0; w < 8; w++) t += wsum[w];
        g_part[slot] = t;
    }
#undef SWOFF
}

// ---------------------------------------------------------------------------
// Final deterministic reduction + sqrt
// ---------------------------------------------------------------------------
__global__ void finalize_kernel(float* __restrict__ out) {
    __shared__ float sh[256];
    const int tid = threadIdx.x;
    float sums[3];
#pragma unroll
    for (int p = 0; p < 3; p++) {
        float s = 0.f;
        for (int idx = tid; idx < NPART; idx += 256)
            s += g_part[p * NPART + idx];
        sh[tid] = s;
        __syncthreads();
        for (int o = 128; o > 0; o >>= 1) {
            if (tid < o) sh[tid] += sh[tid + o];
            __syncthreads();
        }
        sums[p] = sh[0];
        __syncthreads();
    }
    if (tid == 0) {
        double inv = 1.0 / ((double)ROWS * (double)ROWS);
        double mmd = ((double)sums[0] + (double)sums[1] - 2.0 * (double)sums[2]) * inv;
        if (mmd < 0.0) mmd = 0.0;
        out[0] = (float)sqrt(mmd);
    }
}

// ---------------------------------------------------------------------------
extern "C" void kernel_launch(void* const* d_in, const int* in_sizes, int n_in,
                              void* d_out, int out_size) {
    const float* Nf = (const float*)d_in[0];
    const float* Rf = (const float*)d_in[1];
    float* out = (float*)d_out;
    (void)in_sizes; (void)n_in; (void)out_size;

    dim3 pgrid(ROWS / 8, 2, 1);
    prep_kernel<<<pgrid, 256>>>(Nf, Rf);

    dim3 grid(TILES, TILES, 3);
    mmd_mma_kernel<<<grid, 256>>>(Nf, Rf);

    finalize_kernel<<<1, 256>>>(out);
}